// round 14
// baseline (speedup 1.0000x reference)
#include <cuda_runtime.h>
#include <cuda_bf16.h>
#include <cuda_fp16.h>
#include <mma.h>
#include <cstdint>

using namespace nvcuda;

// Problem constants (fixed by the dataset)
#define NN   50000
#define NP   50048          // padded rows: 391 tiles * 128
#define EE   800000
#define CC   128
#define HEADS 4
#define HEAD_DIM 32
#define INV_SQRT_HD 0.17677669529663687f   // 1/sqrt(32)
#define LN_EPS 1e-5f

typedef unsigned long long ull;

// ---------------- device scratch (static, no allocation) ----------------
__device__ float  g_q[NP * CC];          // q fp32, pre-scaled by 1/sqrt(Hd)
// interleaved fp16 kv: per node 256 halves = 32 chunks of (k[4] | v[4])
__device__ __half g_kvh[NP * 256];
__device__ float  g_attnout[NP * CC];    // attention output (fp32)
__device__ int    g_deg[NN];
__device__ int    g_cur[NN];
__device__ int    g_off[NN + 1];
__device__ int    g_edges[EE];           // packed: src | (structure_type << 24)
// W split-precision: [4 weights][k=128][n=128] bf16 (Wq copy pre-scaled)
__device__ __nv_bfloat16 g_w_hi[4 * 128 * 128];
__device__ __nv_bfloat16 g_w_lo[4 * 128 * 128];

// ---------------- smem layout for wmma kernels ----------------
#define A_LD   136                        // bf16 elements per row (pad, mult of 8)
#define TILE_B (128 * A_LD * 2)           // 34816 bytes per bf16 tile
#define SM_AH  0
#define SM_AL  TILE_B                     // 34816
#define SM_BH  (2 * TILE_B)               // 69632
#define SM_BL  (3 * TILE_B)               // 104448
#define SM_BIAS (4 * TILE_B)              // 139264 (float[16][136])
#define SM_TOTAL (SM_BIAS + 16 * 136 * 4) // 147968
#define C_LD   132                        // float stride for C staging

#define NTHREADS 512                      // 16 warps, 1 CTA/SM

// ---------------- zero counters ----------------
__global__ void zero_kernel() {
    int i = blockIdx.x * blockDim.x + threadIdx.x;
    if (i < NN) { g_deg[i] = 0; g_cur[i] = 0; }
}

// ---------------- histogram over dst ----------------
__global__ void hist_kernel(const int* __restrict__ ei) {
    int e = blockIdx.x * blockDim.x + threadIdx.x;
    if (e < EE) atomicAdd(&g_deg[ei[EE + e]], 1);
}

// ---------------- single-block exclusive scan (4 elems/thread) ---------------
__global__ void scan_kernel() {
    __shared__ int wsum[32];
    __shared__ int s_carry;
    const int tid = threadIdx.x, lane = tid & 31, wid = tid >> 5;
    int carry = 0;
    for (int base = 0; base < NN; base += 4096) {
        int i0 = base + tid * 4;
        int v0 = 0, v1 = 0, v2 = 0, v3 = 0;
        if (i0 + 3 < NN) {
            int4 t = *(const int4*)&g_deg[i0];
            v0 = t.x; v1 = t.y; v2 = t.z; v3 = t.w;
        } else {
            if (i0 + 0 < NN) v0 = g_deg[i0 + 0];
            if (i0 + 1 < NN) v1 = g_deg[i0 + 1];
            if (i0 + 2 < NN) v2 = g_deg[i0 + 2];
            if (i0 + 3 < NN) v3 = g_deg[i0 + 3];
        }
        int tot = v0 + v1 + v2 + v3;
        int inc = tot;
        #pragma unroll
        for (int d = 1; d < 32; d <<= 1) {
            int t = __shfl_up_sync(0xffffffffu, inc, d);
            if (lane >= d) inc += t;
        }
        if (lane == 31) wsum[wid] = inc;
        __syncthreads();
        if (wid == 0) {
            int w = wsum[lane];
            int wi = w;
            #pragma unroll
            for (int d = 1; d < 32; d <<= 1) {
                int t = __shfl_up_sync(0xffffffffu, wi, d);
                if (lane >= d) wi += t;
            }
            wsum[lane] = wi - w;   // exclusive warp offset
        }
        __syncthreads();
        int excl = carry + wsum[wid] + inc - tot;
        if (i0 + 0 < NN) g_off[i0 + 0] = excl;
        if (i0 + 1 < NN) g_off[i0 + 1] = excl + v0;
        if (i0 + 2 < NN) g_off[i0 + 2] = excl + v0 + v1;
        if (i0 + 3 < NN) g_off[i0 + 3] = excl + v0 + v1 + v2;
        if (tid == 1023) s_carry = excl + tot;
        __syncthreads();
        carry = s_carry;
    }
    if (tid == 0) g_off[NN] = carry;   // == EE
}

// ---------------- scatter edges into CSR (by dst), pack src+stype ------------
__global__ void scatter_kernel(const int* __restrict__ ei,
                               const int* __restrict__ stype) {
    int e = blockIdx.x * blockDim.x + threadIdx.x;
    if (e >= EE) return;
    int s = ei[e];
    int d = ei[EE + e];
    int pos = atomicAdd(&g_cur[d], 1);
    g_edges[g_off[d] + pos] = s | (stype[s] << 24);
}

// ---------------- W split-precision prep (layout preserved: W[k][n]) ---------
__global__ void wprep_kernel(const float* __restrict__ Wq, const float* __restrict__ Wk,
                             const float* __restrict__ Wv, const float* __restrict__ Wo) {
    int i = blockIdx.x * blockDim.x + threadIdx.x;   // 0 .. 65535
    int w = i >> 14;
    int idx = i & 16383;                             // k*128 + n
    const float* W = (w == 0) ? Wq : (w == 1) ? Wk : (w == 2) ? Wv : Wo;
    float v = W[idx] * ((w == 0) ? INV_SQRT_HD : 1.f);
    __nv_bfloat16 h = __float2bfloat16(v);
    g_w_hi[i] = h;
    g_w_lo[i] = __float2bfloat16(v - __bfloat162float(h));
}

// ---------------- convert fp32 tile rows -> A_hi/A_lo bf16 smem (512 thr) ----
__device__ __forceinline__ void conv_A_tile(const float* __restrict__ A, int row0,
                                            char* sm, int tid) {
    int r = tid >> 2;                 // 0..127
    int c0 = (tid & 3) * 32;
    bool valid = (row0 + r) < NN;
    const float* xr = A + (size_t)(row0 + r) * 128 + c0;
    __nv_bfloat16* ah = (__nv_bfloat16*)(sm + SM_AH) + r * A_LD + c0;
    __nv_bfloat16* al = (__nv_bfloat16*)(sm + SM_AL) + r * A_LD + c0;
    #pragma unroll
    for (int c = 0; c < 32; c += 4) {
        float4 f = valid ? *(const float4*)(xr + c) : make_float4(0.f, 0.f, 0.f, 0.f);
        __nv_bfloat162 h01 = __floats2bfloat162_rn(f.x, f.y);
        __nv_bfloat162 h23 = __floats2bfloat162_rn(f.z, f.w);
        __nv_bfloat162 l01 = __floats2bfloat162_rn(f.x - __low2float(h01),
                                                   f.y - __high2float(h01));
        __nv_bfloat162 l23 = __floats2bfloat162_rn(f.z - __low2float(h23),
                                                   f.w - __high2float(h23));
        *(__nv_bfloat162*)(ah + c)     = h01;
        *(__nv_bfloat162*)(ah + c + 2) = h23;
        *(__nv_bfloat162*)(al + c)     = l01;
        *(__nv_bfloat162*)(al + c + 2) = l23;
    }
}

// ---------------- stage B (hi+lo) for weight widx into smem (512 thr) --------
__device__ __forceinline__ void load_B_tile_sm(int widx, char* sm, int tid) {
    const uint4* sh = (const uint4*)(g_w_hi + widx * 16384);   // 2048 uint4
    const uint4* sl = (const uint4*)(g_w_lo + widx * 16384);
    __nv_bfloat16* bh = (__nv_bfloat16*)(sm + SM_BH);
    __nv_bfloat16* bl = (__nv_bfloat16*)(sm + SM_BL);
    #pragma unroll
    for (int i = tid; i < 2048; i += NTHREADS) {
        int row = i >> 4, col8 = (i & 15) * 8;                 // 16 uint4 per 128-col row
        *(uint4*)(bh + row * A_LD + col8) = sh[i];
        *(uint4*)(bl + row * A_LD + col8) = sl[i];
    }
}

// build replicated bias tile: bias_f[16][136]
__device__ __forceinline__ void build_bias_tile(const float* __restrict__ bias,
                                                char* sm, int tid, float scale) {
    float* bf = (float*)(sm + SM_BIAS);
    for (int idx = tid; idx < 16 * 128; idx += NTHREADS) {
        int r = idx >> 7, c = idx & 127;
        bf[r * 136 + c] = __ldg(&bias[c]) * scale;
    }
}

typedef wmma::fragment<wmma::matrix_a, 16, 16, 16, __nv_bfloat16, wmma::row_major> FragA;
typedef wmma::fragment<wmma::matrix_b, 16, 16, 16, __nv_bfloat16, wmma::row_major> FragB;
typedef wmma::fragment<wmma::accumulator, 16, 16, 16, float> FragC;

// mainloop: acc[2][2] += split-bf16( A_smem x B_smem ), warp tile 32x32
__device__ __forceinline__ void wmma_mainloop(FragC acc[2][2], const char* sm,
                                              int warp_m, int warp_n) {
    const __nv_bfloat16* Ah = (const __nv_bfloat16*)(sm + SM_AH);
    const __nv_bfloat16* Al = (const __nv_bfloat16*)(sm + SM_AL);
    const __nv_bfloat16* Bh = (const __nv_bfloat16*)(sm + SM_BH);
    const __nv_bfloat16* Bl = (const __nv_bfloat16*)(sm + SM_BL);
    for (int k = 0; k < 128; k += 16) {
        FragA ah[2], al[2];
        #pragma unroll
        for (int i = 0; i < 2; i++) {
            int ar = warp_m * 32 + i * 16;
            wmma::load_matrix_sync(ah[i], Ah + ar * A_LD + k, A_LD);
            wmma::load_matrix_sync(al[i], Al + ar * A_LD + k, A_LD);
        }
        #pragma unroll
        for (int j = 0; j < 2; j++) {
            int n0 = warp_n * 32 + j * 16;
            FragB bh, bl;
            wmma::load_matrix_sync(bh, Bh + k * A_LD + n0, A_LD);
            wmma::load_matrix_sync(bl, Bl + k * A_LD + n0, A_LD);
            #pragma unroll
            for (int i = 0; i < 2; i++) {
                wmma::mma_sync(acc[i][j], ah[i], bh, acc[i][j]);
                wmma::mma_sync(acc[i][j], al[i], bh, acc[i][j]);
                wmma::mma_sync(acc[i][j], ah[i], bl, acc[i][j]);
            }
        }
    }
}

// ---------------- QKV wmma GEMM: blockIdx.y selects weight (0=q,1=k,2=v) -----
__global__ __launch_bounds__(NTHREADS)
void qkv_wmma_kernel(const float* __restrict__ x,
                     const float* __restrict__ bq,
                     const float* __restrict__ bk,
                     const float* __restrict__ bv) {
    extern __shared__ char sm[];
    const int tid = threadIdx.x, wid = tid >> 5;
    const int warp_m = wid & 3;          // rows 32*warp_m
    const int warp_n = wid >> 2;         // cols 32*warp_n
    const int row0 = blockIdx.x * 128;
    const int widx = blockIdx.y;         // 0..2

    conv_A_tile(x, row0, sm, tid);
    load_B_tile_sm(widx, sm, tid);
    const float* bias = (widx == 0) ? bq : (widx == 1) ? bk : bv;
    build_bias_tile(bias, sm, tid, (widx == 0) ? INV_SQRT_HD : 1.f);
    __syncthreads();

    FragC acc[2][2];
    const float* bf = (const float*)(sm + SM_BIAS);
    #pragma unroll
    for (int i = 0; i < 2; i++)
        #pragma unroll
        for (int j = 0; j < 2; j++)
            wmma::load_matrix_sync(acc[i][j], bf + warp_n * 32 + j * 16, 136,
                                   wmma::mem_row_major);

    wmma_mainloop(acc, sm, warp_m, warp_n);

    if (widx == 0) {
        // q: direct fp32 store (padded buffer, full-tile store safe)
        #pragma unroll
        for (int i = 0; i < 2; i++)
            #pragma unroll
            for (int j = 0; j < 2; j++) {
                int r = row0 + warp_m * 32 + i * 16;
                wmma::store_matrix_sync(g_q + (size_t)r * 128 + warp_n * 32 + j * 16,
                                        acc[i][j], 128, wmma::mem_row_major);
            }
    } else {
        // k/v: stage fp32 C in (dead) B smem region, then convert to fp16 chunks
        __syncthreads();   // all warps done reading B smem
        float* Cst = (float*)(sm + SM_BH);
        #pragma unroll
        for (int i = 0; i < 2; i++)
            #pragma unroll
            for (int j = 0; j < 2; j++)
                wmma::store_matrix_sync(Cst + (warp_m * 32 + i * 16) * C_LD
                                            + warp_n * 32 + j * 16,
                                        acc[i][j], C_LD, wmma::mem_row_major);
        __syncthreads();
        int r = tid >> 2, c0 = (tid & 3) * 32;
        // interleaved chunk layout: halves (d>>2)*8 + (d&3) for k, +4 for v
        __half* dstrow = g_kvh + (size_t)(row0 + r) * 256 + ((widx == 1) ? 0 : 4);
        const float* srow = Cst + r * C_LD;
        #pragma unroll
        for (int g = 0; g < 8; g++) {
            int c = c0 + g * 4;
            float4 f = *(const float4*)&srow[c];
            __half2 h01 = __floats2half2_rn(f.x, f.y);
            __half2 h23 = __floats2half2_rn(f.z, f.w);
            uint2 u;
            u.x = *(uint32_t*)&h01;
            u.y = *(uint32_t*)&h23;
            *(uint2*)(dstrow + (c >> 2) * 8) = u;
        }
    }
}

// ---------------- fused edge attention: one warp per dst node ----------------
// per edge per lane: ONE uint4 = (k[4]|v[4]) fp16 chunk (512 B/edge total)
__global__ __launch_bounds__(256)
void attn_kernel(const float* __restrict__ sbias) {
    int node = (blockIdx.x * blockDim.x + threadIdx.x) >> 5;
    if (node >= NN) return;
    const int lane = threadIdx.x & 31;
    const int head = lane >> 3;

    const float sb0 = __ldg(&sbias[0 * HEADS + head]);
    const float sb1 = __ldg(&sbias[1 * HEADS + head]);
    const float sb2 = __ldg(&sbias[2 * HEADS + head]);

    const float4 qv = ((const float4*)g_q)[node * 32 + lane];
    const int beg = g_off[node], end = g_off[node + 1];

    float s = 0.f;
    float4 acc = make_float4(0.f, 0.f, 0.f, 0.f);

    int i = beg;
    for (; i + 2 <= end; i += 2) {
        int p0 = g_edges[i];
        int p1 = g_edges[i + 1];
        uint4 u0 = ((const uint4*)(g_kvh + (ull)(p0 & 0x00FFFFFF) * 256))[lane];
        uint4 u1 = ((const uint4*)(g_kvh + (ull)(p1 & 0x00FFFFFF) * 256))[lane];
        float2 k0a = __half22float2(*(__half2*)&u0.x);
        float2 k0b = __half22float2(*(__half2*)&u0.y);
        float2 v0a = __half22float2(*(__half2*)&u0.z);
        float2 v0b = __half22float2(*(__half2*)&u0.w);
        float2 k1a = __half22float2(*(__half2*)&u1.x);
        float2 k1b = __half22float2(*(__half2*)&u1.y);
        float2 v1a = __half22float2(*(__half2*)&u1.z);
        float2 v1b = __half22float2(*(__half2*)&u1.w);
        float d0 = qv.x * k0a.x + qv.y * k0a.y + qv.z * k0b.x + qv.w * k0b.y;
        float d1 = qv.x * k1a.x + qv.y * k1a.y + qv.z * k1b.x + qv.w * k1b.y;
        d0 += __shfl_xor_sync(0xffffffffu, d0, 1);
        d1 += __shfl_xor_sync(0xffffffffu, d1, 1);
        d0 += __shfl_xor_sync(0xffffffffu, d0, 2);
        d1 += __shfl_xor_sync(0xffffffffu, d1, 2);
        d0 += __shfl_xor_sync(0xffffffffu, d0, 4);
        d1 += __shfl_xor_sync(0xffffffffu, d1, 4);
        int st0 = p0 >> 24, st1 = p1 >> 24;
        float b0 = (st0 == 0) ? sb0 : (st0 == 1) ? sb1 : sb2;
        float b1 = (st1 == 0) ? sb0 : (st1 == 1) ? sb1 : sb2;
        float e0 = __expf(d0 + b0);
        float e1 = __expf(d1 + b1);
        s += e0 + e1;
        acc.x += e0 * v0a.x + e1 * v1a.x;
        acc.y += e0 * v0a.y + e1 * v1a.y;
        acc.z += e0 * v0b.x + e1 * v1b.x;
        acc.w += e0 * v0b.y + e1 * v1b.y;
    }
    if (i < end) {
        int p = g_edges[i];
        uint4 u = ((const uint4*)(g_kvh + (ull)(p & 0x00FFFFFF) * 256))[lane];
        float2 ka = __half22float2(*(__half2*)&u.x);
        float2 kb = __half22float2(*(__half2*)&u.y);
        float2 va = __half22float2(*(__half2*)&u.z);
        float2 vb = __half22float2(*(__half2*)&u.w);
        float d = qv.x * ka.x + qv.y * ka.y + qv.z * kb.x + qv.w * kb.y;
        d += __shfl_xor_sync(0xffffffffu, d, 1);
        d += __shfl_xor_sync(0xffffffffu, d, 2);
        d += __shfl_xor_sync(0xffffffffu, d, 4);
        int st = p >> 24;
        float b = (st == 0) ? sb0 : (st == 1) ? sb1 : sb2;
        float e = __expf(d + b);
        s += e;
        acc.x += e * va.x; acc.y += e * va.y;
        acc.z += e * vb.x; acc.w += e * vb.y;
    }
    float inv = 1.f / (s + 1e-16f);
    float4 o = make_float4(acc.x * inv, acc.y * inv, acc.z * inv, acc.w * inv);
    ((float4*)g_attnout)[node * 32 + lane] = o;
}

// ------- O-projection wmma GEMM + residual + LayerNorm ----------------------
__global__ __launch_bounds__(NTHREADS)
void out_ln_kernel(const float* __restrict__ bo,
                   const float* __restrict__ X,
                   const float* __restrict__ gamma,
                   const float* __restrict__ beta,
                   float* __restrict__ out) {
    extern __shared__ char sm[];
    const int tid = threadIdx.x, wid = tid >> 5, lane = tid & 31;
    const int warp_m = wid & 3;
    const int warp_n = wid >> 2;
    const int row0 = blockIdx.x * 128;

    conv_A_tile(g_attnout, row0, sm, tid);
    load_B_tile_sm(3, sm, tid);
    build_bias_tile(bo, sm, tid, 1.f);
    __syncthreads();

    FragC acc[2][2];
    const float* bf = (const float*)(sm + SM_BIAS);
    #pragma unroll
    for (int i = 0; i < 2; i++)
        #pragma unroll
        for (int j = 0; j < 2; j++)
            wmma::load_matrix_sync(acc[i][j], bf + warp_n * 32 + j * 16, 136,
                                   wmma::mem_row_major);

    wmma_mainloop(acc, sm, warp_m, warp_n);

    // stage C into A smem region (A reads done by all warps after sync)
    __syncthreads();
    float* Cst = (float*)(sm + SM_AH);
    #pragma unroll
    for (int i = 0; i < 2; i++)
        #pragma unroll
        for (int j = 0; j < 2; j++)
            wmma::store_matrix_sync(Cst + (warp_m * 32 + i * 16) * C_LD
                                        + warp_n * 32 + j * 16,
                                    acc[i][j], C_LD, wmma::mem_row_major);
    __syncthreads();

    // LayerNorm: warp per row, 8 rows per warp (16 warps)
    float4 g  = *(const float4*)&gamma[lane * 4];
    float4 bt = *(const float4*)&beta[lane * 4];
    for (int rr = wid * 8; rr < wid * 8 + 8; rr++) {
        int r = row0 + rr;
        if (r >= NN) continue;
        float4 cv = *(const float4*)&Cst[rr * C_LD + lane * 4];
        float4 xv = *(const float4*)&X[(size_t)r * 128 + lane * 4];
        float4 y = make_float4(cv.x + xv.x, cv.y + xv.y, cv.z + xv.z, cv.w + xv.w);
        float s1 = y.x + y.y + y.z + y.w;
        float s2 = y.x * y.x + y.y * y.y + y.z * y.z + y.w * y.w;
        #pragma unroll
        for (int m = 16; m >= 1; m >>= 1) {
            s1 += __shfl_xor_sync(0xffffffffu, s1, m);
            s2 += __shfl_xor_sync(0xffffffffu, s2, m);
        }
        float mean = s1 * (1.f / 128.f);
        float var  = s2 * (1.f / 128.f) - mean * mean;
        float rstd = rsqrtf(var + LN_EPS);
        float4 o;
        o.x = (y.x - mean) * rstd * g.x + bt.x;
        o.y = (y.y - mean) * rstd * g.y + bt.y;
        o.z = (y.z - mean) * rstd * g.z + bt.z;
        o.w = (y.w - mean) * rstd * g.w + bt.w;
        *(float4*)&out[(size_t)r * 128 + lane * 4] = o;
    }
}

// ---------------- launch ----------------
extern "C" void kernel_launch(void* const* d_in, const int* in_sizes, int n_in,
                              void* d_out, int out_size) {
    const float* x      = (const float*)d_in[0];
    const int*   stype  = (const int*)  d_in[1];
    const int*   ei     = (const int*)  d_in[2];
    const float* Wq     = (const float*)d_in[3];
    const float* bq     = (const float*)d_in[4];
    const float* Wk     = (const float*)d_in[5];
    const float* bk     = (const float*)d_in[6];
    const float* Wv     = (const float*)d_in[7];
    const float* bv     = (const float*)d_in[8];
    const float* sbias  = (const float*)d_in[9];
    const float* Wo     = (const float*)d_in[10];
    const float* bo     = (const float*)d_in[11];
    const float* gamma  = (const float*)d_in[12];
    const float* beta   = (const float*)d_in[13];
    float* out = (float*)d_out;

    // Unconditional, deterministic, capture-safe (not a stream op).
    cudaFuncSetAttribute(qkv_wmma_kernel, cudaFuncAttributeMaxDynamicSharedMemorySize, SM_TOTAL);
    cudaFuncSetAttribute(out_ln_kernel,   cudaFuncAttributeMaxDynamicSharedMemorySize, SM_TOTAL);

    const int tile_blocks = (NN + 127) / 128;   // 391
    const int edge_blocks = (EE + 255) / 256;
    const int node_blocks = (NN + 255) / 256;

    // CSR build
    zero_kernel<<<node_blocks, 256>>>();
    hist_kernel<<<edge_blocks, 256>>>(ei);
    scan_kernel<<<1, 1024>>>();
    scatter_kernel<<<edge_blocks, 256>>>(ei, stype);

    // weight split-precision prep (4 x 128 x 128, Wq pre-scaled)
    wprep_kernel<<<256, 256>>>(Wq, Wk, Wv, Wo);

    // QKV projections: one CTA per (tile, weight) — 3x parallelism, no serial passes
    qkv_wmma_kernel<<<dim3(tile_blocks, 3), NTHREADS, SM_TOTAL>>>(x, bq, bk, bv);

    // fused segment softmax + aggregation (warp per dst node, fp16 kv chunks)
    attn_kernel<<<(NN * 32 + 255) / 256, 256>>>(sbias);

    // output projection + residual + layernorm: 16 warps/CTA
    out_ln_kernel<<<tile_blocks, NTHREADS, SM_TOTAL>>>(bo, x, gamma, beta, out);
}

// round 15
// speedup vs baseline: 1.5060x; 1.5060x over previous
#include <cuda_runtime.h>
#include <cuda_bf16.h>
#include <cuda_fp16.h>
#include <mma.h>
#include <cstdint>

using namespace nvcuda;

// Problem constants (fixed by the dataset)
#define NN   50000
#define NP   50048          // padded rows: 391 tiles * 128
#define EE   800000
#define CC   128
#define HEADS 4
#define HEAD_DIM 32
#define INV_SQRT_HD 0.17677669529663687f   // 1/sqrt(32)
#define LN_EPS 1e-5f

typedef unsigned long long ull;

// ---------------- device scratch (static, no allocation) ----------------
__device__ float  g_q[NP * CC];          // q fp32, pre-scaled by 1/sqrt(Hd)
// interleaved fp16 kv: per node 256 halves = 32 chunks of (k[4] | v[4])
__device__ __half g_kvh[NP * 256];
__device__ float  g_attnout[NP * CC];    // attention output (fp32)
__device__ int    g_deg[NN];
__device__ int    g_cur[NN];
__device__ int    g_off[NN + 1];
__device__ int    g_edges[EE];           // packed: src | (structure_type << 24)
// W split-precision: [4 weights][k=128][n=128] bf16 (Wq copy pre-scaled)
__device__ __nv_bfloat16 g_w_hi[4 * 128 * 128];
__device__ __nv_bfloat16 g_w_lo[4 * 128 * 128];

// ---------------- smem layout for wmma kernels ----------------
#define A_LD   136                        // bf16 elements per row (pad, mult of 8)
#define TILE_B (128 * A_LD * 2)           // 34816 bytes per bf16 tile
#define SM_AH  0
#define SM_AL  TILE_B                     // 34816
#define SM_BH  (2 * TILE_B)               // 69632
#define SM_BL  (3 * TILE_B)               // 104448
#define SM_BIAS (4 * TILE_B)              // 139264 (float[16][136])
#define SM_TOTAL (SM_BIAS + 16 * 136 * 4) // 147968
#define C_LD   132                        // float stride for C staging

#define NTHREADS 512                      // 16 warps, 1 CTA/SM

// ---------------- zero counters ----------------
__global__ void zero_kernel() {
    int i = blockIdx.x * blockDim.x + threadIdx.x;
    if (i < NN) { g_deg[i] = 0; g_cur[i] = 0; }
}

// ---------------- histogram over dst ----------------
__global__ void hist_kernel(const int* __restrict__ ei) {
    int e = blockIdx.x * blockDim.x + threadIdx.x;
    if (e < EE) atomicAdd(&g_deg[ei[EE + e]], 1);
}

// ---------------- single-block exclusive scan (4 elems/thread) ---------------
__global__ void scan_kernel() {
    __shared__ int wsum[32];
    __shared__ int s_carry;
    const int tid = threadIdx.x, lane = tid & 31, wid = tid >> 5;
    int carry = 0;
    for (int base = 0; base < NN; base += 4096) {
        int i0 = base + tid * 4;
        int v0 = 0, v1 = 0, v2 = 0, v3 = 0;
        if (i0 + 3 < NN) {
            int4 t = *(const int4*)&g_deg[i0];
            v0 = t.x; v1 = t.y; v2 = t.z; v3 = t.w;
        } else {
            if (i0 + 0 < NN) v0 = g_deg[i0 + 0];
            if (i0 + 1 < NN) v1 = g_deg[i0 + 1];
            if (i0 + 2 < NN) v2 = g_deg[i0 + 2];
            if (i0 + 3 < NN) v3 = g_deg[i0 + 3];
        }
        int tot = v0 + v1 + v2 + v3;
        int inc = tot;
        #pragma unroll
        for (int d = 1; d < 32; d <<= 1) {
            int t = __shfl_up_sync(0xffffffffu, inc, d);
            if (lane >= d) inc += t;
        }
        if (lane == 31) wsum[wid] = inc;
        __syncthreads();
        if (wid == 0) {
            int w = wsum[lane];
            int wi = w;
            #pragma unroll
            for (int d = 1; d < 32; d <<= 1) {
                int t = __shfl_up_sync(0xffffffffu, wi, d);
                if (lane >= d) wi += t;
            }
            wsum[lane] = wi - w;   // exclusive warp offset
        }
        __syncthreads();
        int excl = carry + wsum[wid] + inc - tot;
        if (i0 + 0 < NN) g_off[i0 + 0] = excl;
        if (i0 + 1 < NN) g_off[i0 + 1] = excl + v0;
        if (i0 + 2 < NN) g_off[i0 + 2] = excl + v0 + v1;
        if (i0 + 3 < NN) g_off[i0 + 3] = excl + v0 + v1 + v2;
        if (tid == 1023) s_carry = excl + tot;
        __syncthreads();
        carry = s_carry;
    }
    if (tid == 0) g_off[NN] = carry;   // == EE
}

// ---------------- scatter edges into CSR (by dst), pack src+stype ------------
__global__ void scatter_kernel(const int* __restrict__ ei,
                               const int* __restrict__ stype) {
    int e = blockIdx.x * blockDim.x + threadIdx.x;
    if (e >= EE) return;
    int s = ei[e];
    int d = ei[EE + e];
    int pos = atomicAdd(&g_cur[d], 1);
    g_edges[g_off[d] + pos] = s | (stype[s] << 24);
}

// ---------------- W split-precision prep (layout preserved: W[k][n]) ---------
__global__ void wprep_kernel(const float* __restrict__ Wq, const float* __restrict__ Wk,
                             const float* __restrict__ Wv, const float* __restrict__ Wo) {
    int i = blockIdx.x * blockDim.x + threadIdx.x;   // 0 .. 65535
    int w = i >> 14;
    int idx = i & 16383;                             // k*128 + n
    const float* W = (w == 0) ? Wq : (w == 1) ? Wk : (w == 2) ? Wv : Wo;
    float v = W[idx] * ((w == 0) ? INV_SQRT_HD : 1.f);
    __nv_bfloat16 h = __float2bfloat16(v);
    g_w_hi[i] = h;
    g_w_lo[i] = __float2bfloat16(v - __bfloat162float(h));
}

// ---------------- convert fp32 tile rows -> A_hi/A_lo bf16 smem (512 thr) ----
__device__ __forceinline__ void conv_A_tile(const float* __restrict__ A, int row0,
                                            char* sm, int tid) {
    int r = tid >> 2;                 // 0..127
    int c0 = (tid & 3) * 32;
    bool valid = (row0 + r) < NN;
    const float* xr = A + (size_t)(row0 + r) * 128 + c0;
    __nv_bfloat16* ah = (__nv_bfloat16*)(sm + SM_AH) + r * A_LD + c0;
    __nv_bfloat16* al = (__nv_bfloat16*)(sm + SM_AL) + r * A_LD + c0;
    #pragma unroll
    for (int c = 0; c < 32; c += 4) {
        float4 f = valid ? *(const float4*)(xr + c) : make_float4(0.f, 0.f, 0.f, 0.f);
        __nv_bfloat162 h01 = __floats2bfloat162_rn(f.x, f.y);
        __nv_bfloat162 h23 = __floats2bfloat162_rn(f.z, f.w);
        __nv_bfloat162 l01 = __floats2bfloat162_rn(f.x - __low2float(h01),
                                                   f.y - __high2float(h01));
        __nv_bfloat162 l23 = __floats2bfloat162_rn(f.z - __low2float(h23),
                                                   f.w - __high2float(h23));
        *(__nv_bfloat162*)(ah + c)     = h01;
        *(__nv_bfloat162*)(ah + c + 2) = h23;
        *(__nv_bfloat162*)(al + c)     = l01;
        *(__nv_bfloat162*)(al + c + 2) = l23;
    }
}

// ---------------- stage B (hi+lo) for weight widx into smem (512 thr) --------
__device__ __forceinline__ void load_B_tile_sm(int widx, char* sm, int tid) {
    const uint4* sh = (const uint4*)(g_w_hi + widx * 16384);   // 2048 uint4
    const uint4* sl = (const uint4*)(g_w_lo + widx * 16384);
    __nv_bfloat16* bh = (__nv_bfloat16*)(sm + SM_BH);
    __nv_bfloat16* bl = (__nv_bfloat16*)(sm + SM_BL);
    #pragma unroll
    for (int i = tid; i < 2048; i += NTHREADS) {
        int row = i >> 4, col8 = (i & 15) * 8;                 // 16 uint4 per 128-col row
        *(uint4*)(bh + row * A_LD + col8) = sh[i];
        *(uint4*)(bl + row * A_LD + col8) = sl[i];
    }
}

// build replicated bias tile: bias_f[16][136]
__device__ __forceinline__ void build_bias_tile(const float* __restrict__ bias,
                                                char* sm, int tid, float scale) {
    float* bf = (float*)(sm + SM_BIAS);
    for (int idx = tid; idx < 16 * 128; idx += NTHREADS) {
        int r = idx >> 7, c = idx & 127;
        bf[r * 136 + c] = __ldg(&bias[c]) * scale;
    }
}

typedef wmma::fragment<wmma::matrix_a, 16, 16, 16, __nv_bfloat16, wmma::row_major> FragA;
typedef wmma::fragment<wmma::matrix_b, 16, 16, 16, __nv_bfloat16, wmma::row_major> FragB;
typedef wmma::fragment<wmma::accumulator, 16, 16, 16, float> FragC;

// mainloop: acc[2][2] += split-bf16( A_smem x B_smem ), warp tile 32x32
__device__ __forceinline__ void wmma_mainloop(FragC acc[2][2], const char* sm,
                                              int warp_m, int warp_n) {
    const __nv_bfloat16* Ah = (const __nv_bfloat16*)(sm + SM_AH);
    const __nv_bfloat16* Al = (const __nv_bfloat16*)(sm + SM_AL);
    const __nv_bfloat16* Bh = (const __nv_bfloat16*)(sm + SM_BH);
    const __nv_bfloat16* Bl = (const __nv_bfloat16*)(sm + SM_BL);
    for (int k = 0; k < 128; k += 16) {
        FragA ah[2], al[2];
        #pragma unroll
        for (int i = 0; i < 2; i++) {
            int ar = warp_m * 32 + i * 16;
            wmma::load_matrix_sync(ah[i], Ah + ar * A_LD + k, A_LD);
            wmma::load_matrix_sync(al[i], Al + ar * A_LD + k, A_LD);
        }
        #pragma unroll
        for (int j = 0; j < 2; j++) {
            int n0 = warp_n * 32 + j * 16;
            FragB bh, bl;
            wmma::load_matrix_sync(bh, Bh + k * A_LD + n0, A_LD);
            wmma::load_matrix_sync(bl, Bl + k * A_LD + n0, A_LD);
            #pragma unroll
            for (int i = 0; i < 2; i++) {
                wmma::mma_sync(acc[i][j], ah[i], bh, acc[i][j]);
                wmma::mma_sync(acc[i][j], al[i], bh, acc[i][j]);
                wmma::mma_sync(acc[i][j], ah[i], bl, acc[i][j]);
            }
        }
    }
}

// ---------------- fused QKV wmma GEMM: x tile -> q (fp32), kv (fp16) ---------
__global__ __launch_bounds__(NTHREADS)
void qkv_wmma_kernel(const float* __restrict__ x,
                     const float* __restrict__ bq,
                     const float* __restrict__ bk,
                     const float* __restrict__ bv) {
    extern __shared__ char sm[];
    const int tid = threadIdx.x, wid = tid >> 5;
    const int warp_m = wid & 3;          // rows 32*warp_m
    const int warp_n = wid >> 2;         // cols 32*warp_n
    const int row0 = blockIdx.x * 128;

    conv_A_tile(x, row0, sm, tid);

    for (int widx = 0; widx < 3; widx++) {
        __syncthreads();   // prior B/Cst reads complete
        load_B_tile_sm(widx, sm, tid);
        const float* bias = (widx == 0) ? bq : (widx == 1) ? bk : bv;
        build_bias_tile(bias, sm, tid, (widx == 0) ? INV_SQRT_HD : 1.f);
        __syncthreads();

        FragC acc[2][2];
        const float* bf = (const float*)(sm + SM_BIAS);
        #pragma unroll
        for (int i = 0; i < 2; i++)
            #pragma unroll
            for (int j = 0; j < 2; j++)
                wmma::load_matrix_sync(acc[i][j], bf + warp_n * 32 + j * 16, 136,
                                       wmma::mem_row_major);

        wmma_mainloop(acc, sm, warp_m, warp_n);

        if (widx == 0) {
            // q: direct fp32 store (padded buffer, full-tile store safe)
            #pragma unroll
            for (int i = 0; i < 2; i++)
                #pragma unroll
                for (int j = 0; j < 2; j++) {
                    int r = row0 + warp_m * 32 + i * 16;
                    wmma::store_matrix_sync(g_q + (size_t)r * 128 + warp_n * 32 + j * 16,
                                            acc[i][j], 128, wmma::mem_row_major);
                }
        } else {
            // k/v: stage fp32 C in (dead) B smem region, then convert to fp16 chunks
            __syncthreads();   // all warps done reading B smem
            float* Cst = (float*)(sm + SM_BH);
            #pragma unroll
            for (int i = 0; i < 2; i++)
                #pragma unroll
                for (int j = 0; j < 2; j++)
                    wmma::store_matrix_sync(Cst + (warp_m * 32 + i * 16) * C_LD
                                                + warp_n * 32 + j * 16,
                                            acc[i][j], C_LD, wmma::mem_row_major);
            __syncthreads();
            int r = tid >> 2, c0 = (tid & 3) * 32;
            // interleaved chunk layout: halves (d>>2)*8 + (d&3) for k, +4 for v
            __half* dstrow = g_kvh + (size_t)(row0 + r) * 256 + ((widx == 1) ? 0 : 4);
            const float* srow = Cst + r * C_LD;
            #pragma unroll
            for (int g = 0; g < 8; g++) {
                int c = c0 + g * 4;
                float4 f = *(const float4*)&srow[c];
                __half2 h01 = __floats2half2_rn(f.x, f.y);
                __half2 h23 = __floats2half2_rn(f.z, f.w);
                uint2 u;
                u.x = *(uint32_t*)&h01;
                u.y = *(uint32_t*)&h23;
                *(uint2*)(dstrow + (c >> 2) * 8) = u;
            }
        }
    }
}

// ---------------- fused edge attention: one warp per dst node ----------------
// per edge per lane: ONE uint4 = (k[4]|v[4]) fp16 chunk (512 B/edge total)
__global__ __launch_bounds__(256)
void attn_kernel(const float* __restrict__ sbias) {
    int node = (blockIdx.x * blockDim.x + threadIdx.x) >> 5;
    if (node >= NN) return;
    const int lane = threadIdx.x & 31;
    const int head = lane >> 3;

    const float sb0 = __ldg(&sbias[0 * HEADS + head]);
    const float sb1 = __ldg(&sbias[1 * HEADS + head]);
    const float sb2 = __ldg(&sbias[2 * HEADS + head]);

    const float4 qv = ((const float4*)g_q)[node * 32 + lane];
    const int beg = g_off[node], end = g_off[node + 1];

    float s = 0.f;
    float4 acc = make_float4(0.f, 0.f, 0.f, 0.f);

    int i = beg;
    for (; i + 2 <= end; i += 2) {
        int p0 = g_edges[i];
        int p1 = g_edges[i + 1];
        uint4 u0 = ((const uint4*)(g_kvh + (ull)(p0 & 0x00FFFFFF) * 256))[lane];
        uint4 u1 = ((const uint4*)(g_kvh + (ull)(p1 & 0x00FFFFFF) * 256))[lane];
        float2 k0a = __half22float2(*(__half2*)&u0.x);
        float2 k0b = __half22float2(*(__half2*)&u0.y);
        float2 v0a = __half22float2(*(__half2*)&u0.z);
        float2 v0b = __half22float2(*(__half2*)&u0.w);
        float2 k1a = __half22float2(*(__half2*)&u1.x);
        float2 k1b = __half22float2(*(__half2*)&u1.y);
        float2 v1a = __half22float2(*(__half2*)&u1.z);
        float2 v1b = __half22float2(*(__half2*)&u1.w);
        float d0 = qv.x * k0a.x + qv.y * k0a.y + qv.z * k0b.x + qv.w * k0b.y;
        float d1 = qv.x * k1a.x + qv.y * k1a.y + qv.z * k1b.x + qv.w * k1b.y;
        d0 += __shfl_xor_sync(0xffffffffu, d0, 1);
        d1 += __shfl_xor_sync(0xffffffffu, d1, 1);
        d0 += __shfl_xor_sync(0xffffffffu, d0, 2);
        d1 += __shfl_xor_sync(0xffffffffu, d1, 2);
        d0 += __shfl_xor_sync(0xffffffffu, d0, 4);
        d1 += __shfl_xor_sync(0xffffffffu, d1, 4);
        int st0 = p0 >> 24, st1 = p1 >> 24;
        float b0 = (st0 == 0) ? sb0 : (st0 == 1) ? sb1 : sb2;
        float b1 = (st1 == 0) ? sb0 : (st1 == 1) ? sb1 : sb2;
        float e0 = __expf(d0 + b0);
        float e1 = __expf(d1 + b1);
        s += e0 + e1;
        acc.x += e0 * v0a.x + e1 * v1a.x;
        acc.y += e0 * v0a.y + e1 * v1a.y;
        acc.z += e0 * v0b.x + e1 * v1b.x;
        acc.w += e0 * v0b.y + e1 * v1b.y;
    }
    if (i < end) {
        int p = g_edges[i];
        uint4 u = ((const uint4*)(g_kvh + (ull)(p & 0x00FFFFFF) * 256))[lane];
        float2 ka = __half22float2(*(__half2*)&u.x);
        float2 kb = __half22float2(*(__half2*)&u.y);
        float2 va = __half22float2(*(__half2*)&u.z);
        float2 vb = __half22float2(*(__half2*)&u.w);
        float d = qv.x * ka.x + qv.y * ka.y + qv.z * kb.x + qv.w * kb.y;
        d += __shfl_xor_sync(0xffffffffu, d, 1);
        d += __shfl_xor_sync(0xffffffffu, d, 2);
        d += __shfl_xor_sync(0xffffffffu, d, 4);
        int st = p >> 24;
        float b = (st == 0) ? sb0 : (st == 1) ? sb1 : sb2;
        float e = __expf(d + b);
        s += e;
        acc.x += e * va.x; acc.y += e * va.y;
        acc.z += e * vb.x; acc.w += e * vb.y;
    }
    float inv = 1.f / (s + 1e-16f);
    float4 o = make_float4(acc.x * inv, acc.y * inv, acc.z * inv, acc.w * inv);
    ((float4*)g_attnout)[node * 32 + lane] = o;
}

// ------- O-projection wmma GEMM + residual + LayerNorm ----------------------
__global__ __launch_bounds__(NTHREADS)
void out_ln_kernel(const float* __restrict__ bo,
                   const float* __restrict__ X,
                   const float* __restrict__ gamma,
                   const float* __restrict__ beta,
                   float* __restrict__ out) {
    extern __shared__ char sm[];
    const int tid = threadIdx.x, wid = tid >> 5, lane = tid & 31;
    const int warp_m = wid & 3;
    const int warp_n = wid >> 2;
    const int row0 = blockIdx.x * 128;

    conv_A_tile(g_attnout, row0, sm, tid);
    load_B_tile_sm(3, sm, tid);
    build_bias_tile(bo, sm, tid, 1.f);
    __syncthreads();

    FragC acc[2][2];
    const float* bf = (const float*)(sm + SM_BIAS);
    #pragma unroll
    for (int i = 0; i < 2; i++)
        #pragma unroll
        for (int j = 0; j < 2; j++)
            wmma::load_matrix_sync(acc[i][j], bf + warp_n * 32 + j * 16, 136,
                                   wmma::mem_row_major);

    wmma_mainloop(acc, sm, warp_m, warp_n);

    // stage C into A smem region (A reads done by all warps after sync)
    __syncthreads();
    float* Cst = (float*)(sm + SM_AH);
    #pragma unroll
    for (int i = 0; i < 2; i++)
        #pragma unroll
        for (int j = 0; j < 2; j++)
            wmma::store_matrix_sync(Cst + (warp_m * 32 + i * 16) * C_LD
                                        + warp_n * 32 + j * 16,
                                    acc[i][j], C_LD, wmma::mem_row_major);
    __syncthreads();

    // LayerNorm: warp per row, 8 rows per warp (16 warps)
    float4 g  = *(const float4*)&gamma[lane * 4];
    float4 bt = *(const float4*)&beta[lane * 4];
    for (int rr = wid * 8; rr < wid * 8 + 8; rr++) {
        int r = row0 + rr;
        if (r >= NN) continue;
        float4 cv = *(const float4*)&Cst[rr * C_LD + lane * 4];
        float4 xv = *(const float4*)&X[(size_t)r * 128 + lane * 4];
        float4 y = make_float4(cv.x + xv.x, cv.y + xv.y, cv.z + xv.z, cv.w + xv.w);
        float s1 = y.x + y.y + y.z + y.w;
        float s2 = y.x * y.x + y.y * y.y + y.z * y.z + y.w * y.w;
        #pragma unroll
        for (int m = 16; m >= 1; m >>= 1) {
            s1 += __shfl_xor_sync(0xffffffffu, s1, m);
            s2 += __shfl_xor_sync(0xffffffffu, s2, m);
        }
        float mean = s1 * (1.f / 128.f);
        float var  = s2 * (1.f / 128.f) - mean * mean;
        float rstd = rsqrtf(var + LN_EPS);
        float4 o;
        o.x = (y.x - mean) * rstd * g.x + bt.x;
        o.y = (y.y - mean) * rstd * g.y + bt.y;
        o.z = (y.z - mean) * rstd * g.z + bt.z;
        o.w = (y.w - mean) * rstd * g.w + bt.w;
        *(float4*)&out[(size_t)r * 128 + lane * 4] = o;
    }
}

// ---------------- launch ----------------
extern "C" void kernel_launch(void* const* d_in, const int* in_sizes, int n_in,
                              void* d_out, int out_size) {
    const float* x      = (const float*)d_in[0];
    const int*   stype  = (const int*)  d_in[1];
    const int*   ei     = (const int*)  d_in[2];
    const float* Wq     = (const float*)d_in[3];
    const float* bq     = (const float*)d_in[4];
    const float* Wk     = (const float*)d_in[5];
    const float* bk     = (const float*)d_in[6];
    const float* Wv     = (const float*)d_in[7];
    const float* bv     = (const float*)d_in[8];
    const float* sbias  = (const float*)d_in[9];
    const float* Wo     = (const float*)d_in[10];
    const float* bo     = (const float*)d_in[11];
    const float* gamma  = (const float*)d_in[12];
    const float* beta   = (const float*)d_in[13];
    float* out = (float*)d_out;

    // Unconditional, deterministic, capture-safe (not a stream op).
    cudaFuncSetAttribute(qkv_wmma_kernel, cudaFuncAttributeMaxDynamicSharedMemorySize, SM_TOTAL);
    cudaFuncSetAttribute(out_ln_kernel,   cudaFuncAttributeMaxDynamicSharedMemorySize, SM_TOTAL);

    const int tile_blocks = (NN + 127) / 128;   // 391
    const int edge_blocks = (EE + 255) / 256;
    const int node_blocks = (NN + 255) / 256;

    // CSR build
    zero_kernel<<<node_blocks, 256>>>();
    hist_kernel<<<edge_blocks, 256>>>(ei);
    scan_kernel<<<1, 1024>>>();
    scatter_kernel<<<edge_blocks, 256>>>(ei, stype);

    // weight split-precision prep (4 x 128 x 128, Wq pre-scaled)
    wprep_kernel<<<256, 256>>>(Wq, Wk, Wv, Wo);

    // fused QKV projections: 16 warps/CTA, serial 3-pass (R13-best structure)
    qkv_wmma_kernel<<<tile_blocks, NTHREADS, SM_TOTAL>>>(x, bq, bk, bv);

    // fused segment softmax + aggregation (warp per dst node, fp16 kv chunks)
    attn_kernel<<<(NN * 32 + 255) / 256, 256>>>(sbias);

    // output projection + residual + layernorm: 16 warps/CTA
    out_ln_kernel<<<tile_blocks, NTHREADS, SM_TOTAL>>>(bo, x, gamma, beta, out);
}

// round 16
// speedup vs baseline: 1.5313x; 1.0168x over previous
#include <cuda_runtime.h>
#include <cuda_bf16.h>
#include <cuda_fp16.h>
#include <mma.h>
#include <cstdint>

using namespace nvcuda;

// Problem constants (fixed by the dataset)
#define NN   50000
#define NP   50048          // padded rows: 391 tiles * 128
#define EE   800000
#define CC   128
#define HEADS 4
#define HEAD_DIM 32
#define INV_SQRT_HD 0.17677669529663687f   // 1/sqrt(32)
#define LN_EPS 1e-5f

typedef unsigned long long ull;

// ---------------- device scratch (static, no allocation) ----------------
__device__ float  g_q[NP * CC];          // q fp32, pre-scaled by 1/sqrt(Hd)
// interleaved fp16 kv: per node 256 halves = 32 chunks of (k[4] | v[4])
__device__ __half g_kvh[NP * 256];
__device__ float  g_attnout[NP * CC];    // attention output (fp32)
__device__ int    g_deg[NN];
__device__ int    g_cur[NN];
__device__ int    g_off[NN + 1];
__device__ int    g_edges[EE];           // packed: src | (structure_type << 24)
// W split-precision: [4 weights][k=128][n=128] bf16 (Wq copy pre-scaled)
__device__ __nv_bfloat16 g_w_hi[4 * 128 * 128];
__device__ __nv_bfloat16 g_w_lo[4 * 128 * 128];

// ---------------- shared smem layout pieces ----------------
#define A_LD   136                        // bf16 elements per A row (pad)
#define TILE_A (128 * A_LD * 2)           // 34816 bytes per bf16 A tile
#define SM_AH  0
#define SM_AL  TILE_A                     // 34816  (A region ends at 69632)

// ---- qkv kernel layout (wide B: 256 cols, stride 264) ----
#define B2_LD  264
#define SM_B2H 69632
#define SM_B2L (SM_B2H + 128 * B2_LD * 2)      // 137216
#define SM_BIAS2 204800                         // after B2L (ends 204800)
#define BIAS2_LD 264
#define SM_QKV_TOTAL (SM_BIAS2 + 16 * BIAS2_LD * 4)   // 221696
#define C2_LD  260                              // fp32 staging stride (aliases B2)
#define SM_C2  69632                            // 128*260*4 = 133120 <= 135168

// ---- out_ln kernel layout (identical to R15) ----
#define SM_BH  (2 * TILE_A)               // 69632
#define SM_BL  (3 * TILE_A)               // 104448
#define SM_BIAS (4 * TILE_A)              // 139264 (float[16][136])
#define SM_LN_TOTAL (SM_BIAS + 16 * 136 * 4)   // 147968
#define C_LD   132

#define NTHREADS 512                      // 16 warps, 1 CTA/SM

// ---------------- zero counters ----------------
__global__ void zero_kernel() {
    int i = blockIdx.x * blockDim.x + threadIdx.x;
    if (i < NN) { g_deg[i] = 0; g_cur[i] = 0; }
}

// ---------------- histogram over dst ----------------
__global__ void hist_kernel(const int* __restrict__ ei) {
    int e = blockIdx.x * blockDim.x + threadIdx.x;
    if (e < EE) atomicAdd(&g_deg[ei[EE + e]], 1);
}

// ---------------- single-block exclusive scan (4 elems/thread) ---------------
__global__ void scan_kernel() {
    __shared__ int wsum[32];
    __shared__ int s_carry;
    const int tid = threadIdx.x, lane = tid & 31, wid = tid >> 5;
    int carry = 0;
    for (int base = 0; base < NN; base += 4096) {
        int i0 = base + tid * 4;
        int v0 = 0, v1 = 0, v2 = 0, v3 = 0;
        if (i0 + 3 < NN) {
            int4 t = *(const int4*)&g_deg[i0];
            v0 = t.x; v1 = t.y; v2 = t.z; v3 = t.w;
        } else {
            if (i0 + 0 < NN) v0 = g_deg[i0 + 0];
            if (i0 + 1 < NN) v1 = g_deg[i0 + 1];
            if (i0 + 2 < NN) v2 = g_deg[i0 + 2];
            if (i0 + 3 < NN) v3 = g_deg[i0 + 3];
        }
        int tot = v0 + v1 + v2 + v3;
        int inc = tot;
        #pragma unroll
        for (int d = 1; d < 32; d <<= 1) {
            int t = __shfl_up_sync(0xffffffffu, inc, d);
            if (lane >= d) inc += t;
        }
        if (lane == 31) wsum[wid] = inc;
        __syncthreads();
        if (wid == 0) {
            int w = wsum[lane];
            int wi = w;
            #pragma unroll
            for (int d = 1; d < 32; d <<= 1) {
                int t = __shfl_up_sync(0xffffffffu, wi, d);
                if (lane >= d) wi += t;
            }
            wsum[lane] = wi - w;   // exclusive warp offset
        }
        __syncthreads();
        int excl = carry + wsum[wid] + inc - tot;
        if (i0 + 0 < NN) g_off[i0 + 0] = excl;
        if (i0 + 1 < NN) g_off[i0 + 1] = excl + v0;
        if (i0 + 2 < NN) g_off[i0 + 2] = excl + v0 + v1;
        if (i0 + 3 < NN) g_off[i0 + 3] = excl + v0 + v1 + v2;
        if (tid == 1023) s_carry = excl + tot;
        __syncthreads();
        carry = s_carry;
    }
    if (tid == 0) g_off[NN] = carry;   // == EE
}

// ---------------- scatter edges into CSR (by dst), pack src+stype ------------
__global__ void scatter_kernel(const int* __restrict__ ei,
                               const int* __restrict__ stype) {
    int e = blockIdx.x * blockDim.x + threadIdx.x;
    if (e >= EE) return;
    int s = ei[e];
    int d = ei[EE + e];
    int pos = atomicAdd(&g_cur[d], 1);
    g_edges[g_off[d] + pos] = s | (stype[s] << 24);
}

// ---------------- W split-precision prep (layout preserved: W[k][n]) ---------
__global__ void wprep_kernel(const float* __restrict__ Wq, const float* __restrict__ Wk,
                             const float* __restrict__ Wv, const float* __restrict__ Wo) {
    int i = blockIdx.x * blockDim.x + threadIdx.x;   // 0 .. 65535
    int w = i >> 14;
    int idx = i & 16383;                             // k*128 + n
    const float* W = (w == 0) ? Wq : (w == 1) ? Wk : (w == 2) ? Wv : Wo;
    float v = W[idx] * ((w == 0) ? INV_SQRT_HD : 1.f);
    __nv_bfloat16 h = __float2bfloat16(v);
    g_w_hi[i] = h;
    g_w_lo[i] = __float2bfloat16(v - __bfloat162float(h));
}

// ---------------- convert fp32 tile rows -> A_hi/A_lo bf16 smem (512 thr) ----
__device__ __forceinline__ void conv_A_tile(const float* __restrict__ A, int row0,
                                            char* sm, int tid) {
    int r = tid >> 2;                 // 0..127
    int c0 = (tid & 3) * 32;
    bool valid = (row0 + r) < NN;
    const float* xr = A + (size_t)(row0 + r) * 128 + c0;
    __nv_bfloat16* ah = (__nv_bfloat16*)(sm + SM_AH) + r * A_LD + c0;
    __nv_bfloat16* al = (__nv_bfloat16*)(sm + SM_AL) + r * A_LD + c0;
    #pragma unroll
    for (int c = 0; c < 32; c += 4) {
        float4 f = valid ? *(const float4*)(xr + c) : make_float4(0.f, 0.f, 0.f, 0.f);
        __nv_bfloat162 h01 = __floats2bfloat162_rn(f.x, f.y);
        __nv_bfloat162 h23 = __floats2bfloat162_rn(f.z, f.w);
        __nv_bfloat162 l01 = __floats2bfloat162_rn(f.x - __low2float(h01),
                                                   f.y - __high2float(h01));
        __nv_bfloat162 l23 = __floats2bfloat162_rn(f.z - __low2float(h23),
                                                   f.w - __high2float(h23));
        *(__nv_bfloat162*)(ah + c)     = h01;
        *(__nv_bfloat162*)(ah + c + 2) = h23;
        *(__nv_bfloat162*)(al + c)     = l01;
        *(__nv_bfloat162*)(al + c + 2) = l23;
    }
}

typedef wmma::fragment<wmma::matrix_a, 16, 16, 16, __nv_bfloat16, wmma::row_major> FragA;
typedef wmma::fragment<wmma::matrix_b, 16, 16, 16, __nv_bfloat16, wmma::row_major> FragB;
typedef wmma::fragment<wmma::accumulator, 16, 16, 16, float> FragC;

// =================== qkv kernel (wide-B layout, stride B2_LD) ===============

// stage single-weight B (hi+lo) into cols 0..127 of the wide B2 region
__device__ __forceinline__ void load_B2_single(int widx, char* sm, int tid) {
    const uint4* sh = (const uint4*)(g_w_hi + widx * 16384);   // 2048 uint4
    const uint4* sl = (const uint4*)(g_w_lo + widx * 16384);
    __nv_bfloat16* bh = (__nv_bfloat16*)(sm + SM_B2H);
    __nv_bfloat16* bl = (__nv_bfloat16*)(sm + SM_B2L);
    #pragma unroll
    for (int i = tid; i < 2048; i += NTHREADS) {
        int row = i >> 4, col8 = (i & 15) * 8;
        *(uint4*)(bh + row * B2_LD + col8) = sh[i];
        *(uint4*)(bl + row * B2_LD + col8) = sl[i];
    }
}

// stage Wk|Wv side-by-side: cols 0..127 = Wk (widx 1), cols 128..255 = Wv (widx 2)
__device__ __forceinline__ void load_B2_kv(char* sm, int tid) {
    __nv_bfloat16* bh = (__nv_bfloat16*)(sm + SM_B2H);
    __nv_bfloat16* bl = (__nv_bfloat16*)(sm + SM_B2L);
    #pragma unroll
    for (int i = tid; i < 4096; i += NTHREADS) {
        int row  = i >> 5;
        int seg  = (i & 31) >> 4;            // 0 = k-half, 1 = v-half
        int sub  = i & 15;                   // uint4 index within 128 cols
        int col8 = seg * 128 + sub * 8;
        const uint4* sh = (const uint4*)(g_w_hi + (1 + seg) * 16384);
        const uint4* sl = (const uint4*)(g_w_lo + (1 + seg) * 16384);
        *(uint4*)(bh + row * B2_LD + col8) = sh[row * 16 + sub];
        *(uint4*)(bl + row * B2_LD + col8) = sl[row * 16 + sub];
    }
}

// bias tile [16][BIAS2_LD]: single bias (Q, scaled) or bk|bv concatenated
__device__ __forceinline__ void build_bias2_q(const float* __restrict__ bq,
                                              char* sm, int tid) {
    float* bf = (float*)(sm + SM_BIAS2);
    for (int idx = tid; idx < 16 * 128; idx += NTHREADS) {
        int r = idx >> 7, c = idx & 127;
        bf[r * BIAS2_LD + c] = __ldg(&bq[c]) * INV_SQRT_HD;
    }
}
__device__ __forceinline__ void build_bias2_kv(const float* __restrict__ bk,
                                               const float* __restrict__ bv,
                                               char* sm, int tid) {
    float* bf = (float*)(sm + SM_BIAS2);
    for (int idx = tid; idx < 16 * 256; idx += NTHREADS) {
        int r = idx >> 8, c = idx & 255;
        float b = (c < 128) ? __ldg(&bk[c]) : __ldg(&bv[c - 128]);
        bf[r * BIAS2_LD + c] = b;
    }
}

// mainloop over NCOL 16-wide column tiles (NCOL=2 for Q, 4 for KV)
template <int NCOL>
__device__ __forceinline__ void wmma_mainloop2(FragC acc[2][NCOL], const char* sm,
                                               int warp_m, int ncol0) {
    const __nv_bfloat16* Ah = (const __nv_bfloat16*)(sm + SM_AH);
    const __nv_bfloat16* Al = (const __nv_bfloat16*)(sm + SM_AL);
    const __nv_bfloat16* Bh = (const __nv_bfloat16*)(sm + SM_B2H);
    const __nv_bfloat16* Bl = (const __nv_bfloat16*)(sm + SM_B2L);
    for (int k = 0; k < 128; k += 16) {
        FragA ah[2], al[2];
        #pragma unroll
        for (int i = 0; i < 2; i++) {
            int ar = warp_m * 32 + i * 16;
            wmma::load_matrix_sync(ah[i], Ah + ar * A_LD + k, A_LD);
            wmma::load_matrix_sync(al[i], Al + ar * A_LD + k, A_LD);
        }
        #pragma unroll
        for (int j = 0; j < NCOL; j++) {
            int n0 = ncol0 + j * 16;
            FragB bh, bl;
            wmma::load_matrix_sync(bh, Bh + k * B2_LD + n0, B2_LD);
            wmma::load_matrix_sync(bl, Bl + k * B2_LD + n0, B2_LD);
            #pragma unroll
            for (int i = 0; i < 2; i++) {
                wmma::mma_sync(acc[i][j], ah[i], bh, acc[i][j]);
                wmma::mma_sync(acc[i][j], al[i], bh, acc[i][j]);
                wmma::mma_sync(acc[i][j], ah[i], bl, acc[i][j]);
            }
        }
    }
}

// fused QKV: pass0 = Q (N=128), pass1 = K|V merged (N=256) -> fp16 chunks
__global__ __launch_bounds__(NTHREADS)
void qkv_wmma_kernel(const float* __restrict__ x,
                     const float* __restrict__ bq,
                     const float* __restrict__ bk,
                     const float* __restrict__ bv) {
    extern __shared__ char sm[];
    const int tid = threadIdx.x, wid = tid >> 5;
    const int warp_m = wid & 3;
    const int row0 = blockIdx.x * 128;

    conv_A_tile(x, row0, sm, tid);

    // ---------------- pass 0: Q (N=128) ----------------
    load_B2_single(0, sm, tid);
    build_bias2_q(bq, sm, tid);
    __syncthreads();
    {
        const int warp_n = wid >> 2;       // 32-col tile
        FragC acc[2][2];
        const float* bf = (const float*)(sm + SM_BIAS2);
        #pragma unroll
        for (int i = 0; i < 2; i++)
            #pragma unroll
            for (int j = 0; j < 2; j++)
                wmma::load_matrix_sync(acc[i][j], bf + warp_n * 32 + j * 16,
                                       BIAS2_LD, wmma::mem_row_major);
        wmma_mainloop2<2>(acc, sm, warp_m, warp_n * 32);
        #pragma unroll
        for (int i = 0; i < 2; i++)
            #pragma unroll
            for (int j = 0; j < 2; j++) {
                int r = row0 + warp_m * 32 + i * 16;
                wmma::store_matrix_sync(g_q + (size_t)r * 128 + warp_n * 32 + j * 16,
                                        acc[i][j], 128, wmma::mem_row_major);
            }
    }

    // ---------------- pass 1: K|V merged (N=256) ----------------
    __syncthreads();   // all warps done reading pass-0 B
    load_B2_kv(sm, tid);
    build_bias2_kv(bk, bv, sm, tid);
    __syncthreads();
    {
        const int warp_n = wid >> 2;       // 64-col tile over 256
        FragC acc[2][4];
        const float* bf = (const float*)(sm + SM_BIAS2);
        #pragma unroll
        for (int i = 0; i < 2; i++)
            #pragma unroll
            for (int j = 0; j < 4; j++)
                wmma::load_matrix_sync(acc[i][j], bf + warp_n * 64 + j * 16,
                                       BIAS2_LD, wmma::mem_row_major);
        wmma_mainloop2<4>(acc, sm, warp_m, warp_n * 64);

        // stage fp32 C (128 x 256) into the (dead) B2 region
        __syncthreads();
        float* Cst = (float*)(sm + SM_C2);
        #pragma unroll
        for (int i = 0; i < 2; i++)
            #pragma unroll
            for (int j = 0; j < 4; j++)
                wmma::store_matrix_sync(Cst + (warp_m * 32 + i * 16) * C2_LD
                                            + warp_n * 64 + j * 16,
                                        acc[i][j], C2_LD, wmma::mem_row_major);
        __syncthreads();

        // convert to interleaved fp16 chunks: k cols 0..127, v cols 128..255
        int r = tid >> 2, c0 = (tid & 3) * 64;   // 4 threads per row, 64 cols each
        __half* dstrow = g_kvh + (size_t)(row0 + r) * 256;
        const float* srow = Cst + r * C2_LD;
        #pragma unroll
        for (int g = 0; g < 16; g++) {
            int c = c0 + g * 4;
            int isv = (c >= 128);
            int d = c - (isv << 7);              // element index within k or v
            float4 f = *(const float4*)&srow[c];
            __half2 h01 = __floats2half2_rn(f.x, f.y);
            __half2 h23 = __floats2half2_rn(f.z, f.w);
            uint2 u;
            u.x = *(uint32_t*)&h01;
            u.y = *(uint32_t*)&h23;
            *(uint2*)(dstrow + (d >> 2) * 8 + (isv << 2)) = u;
        }
    }
}

// ---------------- fused edge attention: one warp per dst node ----------------
__global__ __launch_bounds__(256)
void attn_kernel(const float* __restrict__ sbias) {
    int node = (blockIdx.x * blockDim.x + threadIdx.x) >> 5;
    if (node >= NN) return;
    const int lane = threadIdx.x & 31;
    const int head = lane >> 3;

    const float sb0 = __ldg(&sbias[0 * HEADS + head]);
    const float sb1 = __ldg(&sbias[1 * HEADS + head]);
    const float sb2 = __ldg(&sbias[2 * HEADS + head]);

    const float4 qv = ((const float4*)g_q)[node * 32 + lane];
    const int beg = g_off[node], end = g_off[node + 1];

    float s = 0.f;
    float4 acc = make_float4(0.f, 0.f, 0.f, 0.f);

    int i = beg;
    for (; i + 2 <= end; i += 2) {
        int p0 = g_edges[i];
        int p1 = g_edges[i + 1];
        uint4 u0 = ((const uint4*)(g_kvh + (ull)(p0 & 0x00FFFFFF) * 256))[lane];
        uint4 u1 = ((const uint4*)(g_kvh + (ull)(p1 & 0x00FFFFFF) * 256))[lane];
        float2 k0a = __half22float2(*(__half2*)&u0.x);
        float2 k0b = __half22float2(*(__half2*)&u0.y);
        float2 v0a = __half22float2(*(__half2*)&u0.z);
        float2 v0b = __half22float2(*(__half2*)&u0.w);
        float2 k1a = __half22float2(*(__half2*)&u1.x);
        float2 k1b = __half22float2(*(__half2*)&u1.y);
        float2 v1a = __half22float2(*(__half2*)&u1.z);
        float2 v1b = __half22float2(*(__half2*)&u1.w);
        float d0 = qv.x * k0a.x + qv.y * k0a.y + qv.z * k0b.x + qv.w * k0b.y;
        float d1 = qv.x * k1a.x + qv.y * k1a.y + qv.z * k1b.x + qv.w * k1b.y;
        d0 += __shfl_xor_sync(0xffffffffu, d0, 1);
        d1 += __shfl_xor_sync(0xffffffffu, d1, 1);
        d0 += __shfl_xor_sync(0xffffffffu, d0, 2);
        d1 += __shfl_xor_sync(0xffffffffu, d1, 2);
        d0 += __shfl_xor_sync(0xffffffffu, d0, 4);
        d1 += __shfl_xor_sync(0xffffffffu, d1, 4);
        int st0 = p0 >> 24, st1 = p1 >> 24;
        float b0 = (st0 == 0) ? sb0 : (st0 == 1) ? sb1 : sb2;
        float b1 = (st1 == 0) ? sb0 : (st1 == 1) ? sb1 : sb2;
        float e0 = __expf(d0 + b0);
        float e1 = __expf(d1 + b1);
        s += e0 + e1;
        acc.x += e0 * v0a.x + e1 * v1a.x;
        acc.y += e0 * v0a.y + e1 * v1a.y;
        acc.z += e0 * v0b.x + e1 * v1b.x;
        acc.w += e0 * v0b.y + e1 * v1b.y;
    }
    if (i < end) {
        int p = g_edges[i];
        uint4 u = ((const uint4*)(g_kvh + (ull)(p & 0x00FFFFFF) * 256))[lane];
        float2 ka = __half22float2(*(__half2*)&u.x);
        float2 kb = __half22float2(*(__half2*)&u.y);
        float2 va = __half22float2(*(__half2*)&u.z);
        float2 vb = __half22float2(*(__half2*)&u.w);
        float d = qv.x * ka.x + qv.y * ka.y + qv.z * kb.x + qv.w * kb.y;
        d += __shfl_xor_sync(0xffffffffu, d, 1);
        d += __shfl_xor_sync(0xffffffffu, d, 2);
        d += __shfl_xor_sync(0xffffffffu, d, 4);
        int st = p >> 24;
        float b = (st == 0) ? sb0 : (st == 1) ? sb1 : sb2;
        float e = __expf(d + b);
        s += e;
        acc.x += e * va.x; acc.y += e * va.y;
        acc.z += e * vb.x; acc.w += e * vb.y;
    }
    float inv = 1.f / (s + 1e-16f);
    float4 o = make_float4(acc.x * inv, acc.y * inv, acc.z * inv, acc.w * inv);
    ((float4*)g_attnout)[node * 32 + lane] = o;
}

// ===== out_ln: byte-identical structure to the R15 kernel =====
__device__ __forceinline__ void load_B_tile_sm(int widx, char* sm, int tid) {
    const uint4* sh = (const uint4*)(g_w_hi + widx * 16384);
    const uint4* sl = (const uint4*)(g_w_lo + widx * 16384);
    __nv_bfloat16* bh = (__nv_bfloat16*)(sm + SM_BH);
    __nv_bfloat16* bl = (__nv_bfloat16*)(sm + SM_BL);
    #pragma unroll
    for (int i = tid; i < 2048; i += NTHREADS) {
        int row = i >> 4, col8 = (i & 15) * 8;
        *(uint4*)(bh + row * A_LD + col8) = sh[i];
        *(uint4*)(bl + row * A_LD + col8) = sl[i];
    }
}
__device__ __forceinline__ void build_bias_tile(const float* __restrict__ bias,
                                                char* sm, int tid, float scale) {
    float* bf = (float*)(sm + SM_BIAS);
    for (int idx = tid; idx < 16 * 128; idx += NTHREADS) {
        int r = idx >> 7, c = idx & 127;
        bf[r * 136 + c] = __ldg(&bias[c]) * scale;
    }
}
__device__ __forceinline__ void wmma_mainloop(FragC acc[2][2], const char* sm,
                                              int warp_m, int warp_n) {
    const __nv_bfloat16* Ah = (const __nv_bfloat16*)(sm + SM_AH);
    const __nv_bfloat16* Al = (const __nv_bfloat16*)(sm + SM_AL);
    const __nv_bfloat16* Bh = (const __nv_bfloat16*)(sm + SM_BH);
    const __nv_bfloat16* Bl = (const __nv_bfloat16*)(sm + SM_BL);
    for (int k = 0; k < 128; k += 16) {
        FragA ah[2], al[2];
        #pragma unroll
        for (int i = 0; i < 2; i++) {
            int ar = warp_m * 32 + i * 16;
            wmma::load_matrix_sync(ah[i], Ah + ar * A_LD + k, A_LD);
            wmma::load_matrix_sync(al[i], Al + ar * A_LD + k, A_LD);
        }
        #pragma unroll
        for (int j = 0; j < 2; j++) {
            int n0 = warp_n * 32 + j * 16;
            FragB bh, bl;
            wmma::load_matrix_sync(bh, Bh + k * A_LD + n0, A_LD);
            wmma::load_matrix_sync(bl, Bl + k * A_LD + n0, A_LD);
            #pragma unroll
            for (int i = 0; i < 2; i++) {
                wmma::mma_sync(acc[i][j], ah[i], bh, acc[i][j]);
                wmma::mma_sync(acc[i][j], al[i], bh, acc[i][j]);
                wmma::mma_sync(acc[i][j], ah[i], bl, acc[i][j]);
            }
        }
    }
}

__global__ __launch_bounds__(NTHREADS)
void out_ln_kernel(const float* __restrict__ bo,
                   const float* __restrict__ X,
                   const float* __restrict__ gamma,
                   const float* __restrict__ beta,
                   float* __restrict__ out) {
    extern __shared__ char sm[];
    const int tid = threadIdx.x, wid = tid >> 5, lane = tid & 31;
    const int warp_m = wid & 3;
    const int warp_n = wid >> 2;
    const int row0 = blockIdx.x * 128;

    conv_A_tile(g_attnout, row0, sm, tid);
    load_B_tile_sm(3, sm, tid);
    build_bias_tile(bo, sm, tid, 1.f);
    __syncthreads();

    FragC acc[2][2];
    const float* bf = (const float*)(sm + SM_BIAS);
    #pragma unroll
    for (int i = 0; i < 2; i++)
        #pragma unroll
        for (int j = 0; j < 2; j++)
            wmma::load_matrix_sync(acc[i][j], bf + warp_n * 32 + j * 16, 136,
                                   wmma::mem_row_major);

    wmma_mainloop(acc, sm, warp_m, warp_n);

    __syncthreads();
    float* Cst = (float*)(sm + SM_AH);
    #pragma unroll
    for (int i = 0; i < 2; i++)
        #pragma unroll
        for (int j = 0; j < 2; j++)
            wmma::store_matrix_sync(Cst + (warp_m * 32 + i * 16) * C_LD
                                        + warp_n * 32 + j * 16,
                                    acc[i][j], C_LD, wmma::mem_row_major);
    __syncthreads();

    float4 g  = *(const float4*)&gamma[lane * 4];
    float4 bt = *(const float4*)&beta[lane * 4];
    for (int rr = wid * 8; rr < wid * 8 + 8; rr++) {
        int r = row0 + rr;
        if (r >= NN) continue;
        float4 cv = *(const float4*)&Cst[rr * C_LD + lane * 4];
        float4 xv = *(const float4*)&X[(size_t)r * 128 + lane * 4];
        float4 y = make_float4(cv.x + xv.x, cv.y + xv.y, cv.z + xv.z, cv.w + xv.w);
        float s1 = y.x + y.y + y.z + y.w;
        float s2 = y.x * y.x + y.y * y.y + y.z * y.z + y.w * y.w;
        #pragma unroll
        for (int m = 16; m >= 1; m >>= 1) {
            s1 += __shfl_xor_sync(0xffffffffu, s1, m);
            s2 += __shfl_xor_sync(0xffffffffu, s2, m);
        }
        float mean = s1 * (1.f / 128.f);
        float var  = s2 * (1.f / 128.f) - mean * mean;
        float rstd = rsqrtf(var + LN_EPS);
        float4 o;
        o.x = (y.x - mean) * rstd * g.x + bt.x;
        o.y = (y.y - mean) * rstd * g.y + bt.y;
        o.z = (y.z - mean) * rstd * g.z + bt.z;
        o.w = (y.w - mean) * rstd * g.w + bt.w;
        *(float4*)&out[(size_t)r * 128 + lane * 4] = o;
    }
}

// ---------------- launch ----------------
extern "C" void kernel_launch(void* const* d_in, const int* in_sizes, int n_in,
                              void* d_out, int out_size) {
    const float* x      = (const float*)d_in[0];
    const int*   stype  = (const int*)  d_in[1];
    const int*   ei     = (const int*)  d_in[2];
    const float* Wq     = (const float*)d_in[3];
    const float* bq     = (const float*)d_in[4];
    const float* Wk     = (const float*)d_in[5];
    const float* bk     = (const float*)d_in[6];
    const float* Wv     = (const float*)d_in[7];
    const float* bv     = (const float*)d_in[8];
    const float* sbias  = (const float*)d_in[9];
    const float* Wo     = (const float*)d_in[10];
    const float* bo     = (const float*)d_in[11];
    const float* gamma  = (const float*)d_in[12];
    const float* beta   = (const float*)d_in[13];
    float* out = (float*)d_out;

    // Unconditional, deterministic, capture-safe (not a stream op).
    cudaFuncSetAttribute(qkv_wmma_kernel, cudaFuncAttributeMaxDynamicSharedMemorySize, SM_QKV_TOTAL);
    cudaFuncSetAttribute(out_ln_kernel,   cudaFuncAttributeMaxDynamicSharedMemorySize, SM_LN_TOTAL);

    const int tile_blocks = (NN + 127) / 128;   // 391
    const int edge_blocks = (EE + 255) / 256;
    const int node_blocks = (NN + 255) / 256;

    // CSR build
    zero_kernel<<<node_blocks, 256>>>();
    hist_kernel<<<edge_blocks, 256>>>(ei);
    scan_kernel<<<1, 1024>>>();
    scatter_kernel<<<edge_blocks, 256>>>(ei, stype);

    // weight split-precision prep (4 x 128 x 128, Wq pre-scaled)
    wprep_kernel<<<256, 256>>>(Wq, Wk, Wv, Wo);

    // fused QKV projections: pass0 = Q, pass1 = K|V merged (N=256)
    qkv_wmma_kernel<<<tile_blocks, NTHREADS, SM_QKV_TOTAL>>>(x, bq, bk, bv);

    // fused segment softmax + aggregation (warp per dst node, fp16 kv chunks)
    attn_kernel<<<(NN * 32 + 255) / 256, 256>>>(sbias);

    // output projection + residual + layernorm
    out_ln_kernel<<<tile_blocks, NTHREADS, SM_LN_TOTAL>>>(bo, x, gamma, beta, out);
}